// round 10
// baseline (speedup 1.0000x reference)
#include <cuda_runtime.h>
#include <cstdint>

// ---------------------------------------------------------------------------
// Problem constants
// ---------------------------------------------------------------------------
#define L_NUM 2
#define HS    512
#define BB    64
#define SS    1024
#define INW   512
#define ROWS  1024            // 2 gates * HS, interleaved: r = 2*h + g' (g': 0=z, 1=n)
#define SEQ_ELEMS (BB*SS*HS)

// Scan partition: 2 layers x 4 batch-groups (16 b) x 16 row-groups (64 rows)
#define NBG   4
#define GSIZE 16              // CTAs per cluster (= barrier group)

// ---------------------------------------------------------------------------
// Device scratch
// ---------------------------------------------------------------------------
__device__ __align__(16) float g_WG  [L_NUM*ROWS*INW];             // [l][r][i] tf32-rounded
__device__ __align__(16) float g_UG  [L_NUM*ROWS*HS];              // [l][r][o] tf32-rounded
__device__ __align__(16) float g_bias[L_NUM*ROWS];
__device__ __align__(16) float g_Gx  [(size_t)SS*L_NUM*BB*ROWS];   // 512 MB [t][l][b][r]
__device__ __align__(16) float g_Hbuf[2*L_NUM*BB*HS];              // ping-pong [p][l][b][o]

__device__ __forceinline__ float rna_tf32(float x) {
    uint32_t r;
    asm("cvt.rna.tf32.f32 %0, %1;" : "=r"(r) : "f"(x));
    return __uint_as_float(r);
}

// D (4xf32) += A (m16k8 tf32, row-major) * B (k8n8 tf32, col-major)
__device__ __forceinline__ void mma_tf32(float* d, const uint32_t* a, const uint32_t* bf) {
    asm volatile(
        "mma.sync.aligned.m16n8k8.row.col.f32.tf32.tf32.f32 "
        "{%0,%1,%2,%3}, {%4,%5,%6,%7}, {%8,%9}, {%0,%1,%2,%3};"
        : "+f"(d[0]), "+f"(d[1]), "+f"(d[2]), "+f"(d[3])
        : "r"(a[0]), "r"(a[1]), "r"(a[2]), "r"(a[3]), "r"(bf[0]), "r"(bf[1]));
}

__device__ __forceinline__ void cp16(void* s, const void* g) {
    uint32_t sa = (uint32_t)__cvta_generic_to_shared(s);
    asm volatile("cp.async.cg.shared.global [%0], [%1], 16;" :: "r"(sa), "l"(g));
}

// ---------------------------------------------------------------------------
// Kernel A: combined weights (tf32-rounded) + biases
// ---------------------------------------------------------------------------
__global__ void combine_kernel(const float* __restrict__ W1, const float* __restrict__ W2,
                               const float* __restrict__ U1, const float* __restrict__ U2,
                               const float* __restrict__ dW1, const float* __restrict__ dW2,
                               const float* __restrict__ dU1, const float* __restrict__ dU2,
                               const float* __restrict__ b1, const float* __restrict__ b2)
{
    int idx = blockIdx.x * blockDim.x + threadIdx.x;   // L*ROWS*INW threads
    int l   = idx >> 19;
    int rem = idx & 524287;
    int r   = rem >> 9;
    int i   = rem & 511;
    int h   = r >> 1;
    int g   = (r & 1) + 1;                             // original gate (1=z, 2=n)

    float w1  = W1 [l*3 + g];
    float dw1 = dW1[l*3 + g];
    float u1  = U1 [l*3 + g];
    float du1 = dU1[l*3 + g];
    int src = (l*HS + h)*INW + i;
    g_WG[idx] = rna_tf32(w1*W2[src] + dw1*dW2[src]);
    g_UG[idx] = rna_tf32(u1*U2[src] + du1*dU2[src]);

    if (idx < L_NUM*ROWS) {
        int ll = idx >> 10;
        int rr = idx & 1023;
        int hh = rr >> 1;
        int gg = (rr & 1) + 1;
        g_bias[idx] = b1[ll*3*HS + gg*HS + hh] + b2[ll*3*HS + gg*HS + hh];
    }
}

// ---------------------------------------------------------------------------
// Init: h0 (L,B,HS) -> Hbuf[0][l][b][h] (same layout, direct copy)
// ---------------------------------------------------------------------------
__global__ void init_h_kernel(const float* __restrict__ h0)
{
    int idx = blockIdx.x * blockDim.x + threadIdx.x;   // 65536 threads
    g_Hbuf[idx] = h0[idx];
}

// ---------------------------------------------------------------------------
// Kernel B: tf32 mma GEMM with cp.async double buffering.
//   Gx[t][l][b][r] = sum_i x[b][t][i] * WG[l][r][i]
//   grid (1024, 8, 2); 8 warps: (wid&3)=m16 b-tile, (wid>>2)=64-wide r half.
//   x is fed raw (tf32 HW truncation); W pre-rounded rna.
// ---------------------------------------------------------------------------
#define APITCH 36
#define ABUF   (64*APITCH)     // 2304 floats
#define BBUF   (128*APITCH)    // 4608 floats
#define GEMM_SMEM ((2*ABUF + 2*BBUF)*4)   // 55296 B

__global__ void __launch_bounds__(256) gemm_x_kernel(const float* __restrict__ x)
{
    const int t  = blockIdx.x;
    const int rb = blockIdx.y * 128;
    const int l  = blockIdx.z;

    extern __shared__ __align__(16) float smem[];
    float* As = smem;                  // [2][64][36]
    float* Bs = smem + 2*ABUF;         // [2][128][36]

    const int tid  = threadIdx.x;
    const int wid  = tid >> 5;
    const int lane = tid & 31;
    const int g    = lane >> 2;
    const int tq   = lane & 3;
    const int m0   = (wid & 3) * 16;
    const int nb0  = (wid >> 2) * 64;

    const float* xa = x + (size_t)t * INW;                    // + b*SS*INW + k
    const float* wb = g_WG + ((size_t)l*ROWS + rb) * INW;     // + r*INW + k

    // stage indices (fixed per thread)
    const int sa_b  = tid >> 3, sa_k = tid & 7;               // As: 2 cp16 each
    const int sb_r  = tid >> 3, sb_k = tid & 7;               // Bs: 4 cp16 each

    auto stage = [&](int buf, int k0) {
        float* Ad = As + buf*ABUF;
        float* Bd = Bs + buf*BBUF;
        #pragma unroll
        for (int q = 0; q < 2; ++q) {
            int b = sa_b + q*32;
            cp16(&Ad[b*APITCH + sa_k*4], xa + (size_t)b*SS*INW + k0 + sa_k*4);
        }
        #pragma unroll
        for (int q = 0; q < 4; ++q) {
            int r = sb_r + q*32;
            cp16(&Bd[r*APITCH + sb_k*4], wb + (size_t)r*INW + k0 + sb_k*4);
        }
        asm volatile("cp.async.commit_group;" ::: "memory");
    };

    float acc[8][4];
    #pragma unroll
    for (int nt = 0; nt < 8; ++nt)
        #pragma unroll
        for (int j = 0; j < 4; ++j) acc[nt][j] = 0.0f;

    stage(0, 0);

    for (int ki = 0; ki < 16; ++ki) {
        if (ki < 15) {
            stage((ki+1) & 1, (ki+1)*32);
            asm volatile("cp.async.wait_group 1;" ::: "memory");
        } else {
            asm volatile("cp.async.wait_group 0;" ::: "memory");
        }
        __syncthreads();

        const float* Ab = As + (ki & 1)*ABUF;
        const float* Bb = Bs + (ki & 1)*BBUF;
        #pragma unroll
        for (int ksi = 0; ksi < 4; ++ksi) {
            int kk = ksi*8;
            uint32_t a[4];
            a[0] = __float_as_uint(Ab[(m0+g  )*APITCH + kk + tq    ]);
            a[1] = __float_as_uint(Ab[(m0+g+8)*APITCH + kk + tq    ]);
            a[2] = __float_as_uint(Ab[(m0+g  )*APITCH + kk + tq + 4]);
            a[3] = __float_as_uint(Ab[(m0+g+8)*APITCH + kk + tq + 4]);
            #pragma unroll
            for (int nt = 0; nt < 8; ++nt) {
                int nrow = nb0 + nt*8 + g;
                uint32_t bf[2];
                bf[0] = __float_as_uint(Bb[nrow*APITCH + kk + tq    ]);
                bf[1] = __float_as_uint(Bb[nrow*APITCH + kk + tq + 4]);
                mma_tf32(acc[nt], a, bf);
            }
        }
        __syncthreads();
    }

    float* gout = g_Gx + ((size_t)(t*L_NUM + l)*BB) * ROWS + rb;
    #pragma unroll
    for (int nt = 0; nt < 8; ++nt) {
        int r = nb0 + nt*8 + 2*tq;
        __stcs((float2*)&gout[(size_t)(m0+g  )*ROWS + r], make_float2(acc[nt][0], acc[nt][1]));
        __stcs((float2*)&gout[(size_t)(m0+g+8)*ROWS + r], make_float2(acc[nt][2], acc[nt][3]));
    }
}

// ---------------------------------------------------------------------------
// Kernel C: persistent scan, cluster-16 hardware barrier.
//   CTA (l, bg, j): 16 batches, 64 rows -> m16(b) x n64(r) x k512.
//   512 thr = 16 warps: (wid&1)=k half, (wid>>1)=n8 row tile.
//   UG B-frags in 64 regs/thread (whole kernel). hold carried in a register.
//   Barrier: barrier.cluster.arrive (release) / wait (acquire), split around
//   the next step's gx prefetch.
// ---------------------------------------------------------------------------
__global__ void __launch_bounds__(512, 1) step_kernel(float* __restrict__ out)
{
    const int tid  = threadIdx.x;
    const int lane = tid & 31;
    const int wid  = tid >> 5;
    const int g    = lane >> 2;
    const int tq   = lane & 3;

    const int bid  = blockIdx.x;
    const int l    = bid >> 6;
    const int bg   = (bid >> 4) & 3;
    const int j    = bid & 15;
    const int rbase = j * 64;
    const int hbase = j * 32;

    const int ks    = wid & 1;          // k half
    const int nt    = wid >> 1;         // n8 tile (0..7)
    const int kbase = ks * 256;
    const int rW    = rbase + nt*8;

    __shared__ __align__(16) float Hs  [16*516];     // 33.0 KB  [bl][o]
    __shared__ __align__(16) float Dred[2*16*66];    //  8.4 KB  [ks][bl][r64]

    // --- hoist UG B-frags into registers ---
    uint32_t breg[32][2];
    {
        const float* ug = g_UG + ((size_t)l*ROWS + rW + g)*HS + kbase;
        #pragma unroll
        for (int m = 0; m < 32; ++m) {
            breg[m][0] = __float_as_uint(ug[m*8 + tq    ]);
            breg[m][1] = __float_as_uint(ug[m*8 + tq + 4]);
        }
    }

    // update-phase identity: one (h, b) pair per thread
    const int hh = tid & 31;
    const int bl = tid >> 5;
    const int bglob = bg*16 + bl;
    const float bz = g_bias[l*ROWS + rbase + 2*hh];
    const float bn = g_bias[l*ROWS + rbase + 2*hh + 1];

    // hold carried in a register: this thread produced this (h,b) last step
    float hold = __ldg(&g_Hbuf[(size_t)l*BB*HS + (size_t)bglob*HS + hbase + hh]);

    float* outSeq   = out;
    float* outState = out + (size_t)SEQ_ELEMS;

    const float* gxbase = g_Gx + (size_t)l*BB*ROWS + (size_t)bglob*ROWS + rbase + 2*hh;
    float2 gxv = __ldcs((const float2*)gxbase);      // t = 0

    int p = 0;
    for (int t = 0; t < SS; ++t) {
        const float* Hrd = g_Hbuf + (size_t)(p*L_NUM + l)*BB*HS;       // [b][o]
        float*       Hwr = g_Hbuf + (size_t)((1-p)*L_NUM + l)*BB*HS;

        // --- stage H slice: 16 b x 512 o, tf32-rounded, pitch 516 ---
        #pragma unroll
        for (int q = 0; q < 4; ++q) {
            int i4   = tid + q*512;
            int row  = i4 >> 7;
            int col4 = i4 & 127;
            float4 v = __ldcg((const float4*)(Hrd + (size_t)(bg*16 + row)*HS + col4*4));
            v.x = rna_tf32(v.x); v.y = rna_tf32(v.y);
            v.z = rna_tf32(v.z); v.w = rna_tf32(v.w);
            *(float4*)&Hs[row*516 + col4*4] = v;
        }
        __syncthreads();

        // --- mma: m16(b) x n8(r) x k256 per warp ---
        float acc0[4] = {0,0,0,0};
        float acc1[4] = {0,0,0,0};
        #pragma unroll
        for (int m = 0; m < 32; ++m) {
            int ko = kbase + m*8;
            uint32_t a[4];
            a[0] = __float_as_uint(Hs[(g  )*516 + ko + tq    ]);
            a[1] = __float_as_uint(Hs[(g+8)*516 + ko + tq    ]);
            a[2] = __float_as_uint(Hs[(g  )*516 + ko + tq + 4]);
            a[3] = __float_as_uint(Hs[(g+8)*516 + ko + tq + 4]);
            if (m & 1) mma_tf32(acc1, a, breg[m]);
            else       mma_tf32(acc0, a, breg[m]);
        }
        {
            float* dr = &Dred[(ks*16 + g)*66 + nt*8 + 2*tq];
            *(float2*)dr          = make_float2(acc0[0]+acc1[0], acc0[1]+acc1[1]);
            *(float2*)(dr + 8*66) = make_float2(acc0[2]+acc1[2], acc0[3]+acc1[3]);
        }
        __syncthreads();

        // --- fused update: one (hh, bl) per thread ---
        {
            float2 d0 = *(const float2*)&Dred[(     bl)*66 + 2*hh];
            float2 d1 = *(const float2*)&Dred[(16 + bl)*66 + 2*hh];
            float gz = d0.x + d1.x + gxv.x + bz;
            float gn = d0.y + d1.y + gxv.y + bn;
            float z = __fdividef(1.0f, 1.0f + __expf(-gz));
            float n = 1.0f - __fdividef(2.0f, __expf(2.0f*gn) + 1.0f);
            float hnew = (1.0f - z)*n + z*hold;
            hold = hnew;
            Hwr[(size_t)bglob*HS + hbase + hh] = hnew;
            if (l == 1)
                outSeq[((size_t)bglob*SS + t)*HS + hbase + hh] = hnew;
            if (t == SS-1)
                outState[((size_t)l*BB + bglob)*HS + hbase + hh] = hnew;
        }

        // --- cluster barrier (release at arrive / acquire at wait) ---
        asm volatile("barrier.cluster.arrive.aligned;" ::: "memory");
        if (t + 1 < SS)
            gxv = __ldcs((const float2*)(gxbase + (size_t)(t+1)*L_NUM*BB*ROWS));
        asm volatile("barrier.cluster.wait.aligned;" ::: "memory");
        p ^= 1;
    }
}

// ---------------------------------------------------------------------------
// Launch
// ---------------------------------------------------------------------------
extern "C" void kernel_launch(void* const* d_in, const int* in_sizes, int n_in,
                              void* d_out, int out_size)
{
    const float* x   = (const float*)d_in[0];
    const float* h0  = (const float*)d_in[1];
    const float* W1  = (const float*)d_in[2];
    const float* W2  = (const float*)d_in[3];
    const float* U1  = (const float*)d_in[4];
    const float* U2  = (const float*)d_in[5];
    const float* dW1 = (const float*)d_in[6];
    const float* dW2 = (const float*)d_in[7];
    const float* dU1 = (const float*)d_in[8];
    const float* dU2 = (const float*)d_in[9];
    const float* b1  = (const float*)d_in[10];
    const float* b2  = (const float*)d_in[11];
    float* out = (float*)d_out;

    combine_kernel<<<4096, 256>>>(W1, W2, U1, U2, dW1, dW2, dU1, dU2, b1, b2);
    init_h_kernel<<<256, 256>>>(h0);

    cudaFuncSetAttribute(gemm_x_kernel, cudaFuncAttributeMaxDynamicSharedMemorySize, GEMM_SMEM);
    dim3 gg(1024, 8, 2);
    gemm_x_kernel<<<gg, 256, GEMM_SMEM>>>(x);

    // persistent scan as 8 clusters of 16 CTAs (nonportable cluster size)
    cudaFuncSetAttribute(step_kernel, cudaFuncAttributeNonPortableClusterSizeAllowed, 1);
    cudaLaunchConfig_t cfg = {};
    cfg.gridDim  = dim3(128, 1, 1);
    cfg.blockDim = dim3(512, 1, 1);
    cfg.dynamicSmemBytes = 0;
    cfg.stream = 0;
    cudaLaunchAttribute attrs[1];
    attrs[0].id = cudaLaunchAttributeClusterDimension;
    attrs[0].val.clusterDim.x = GSIZE;
    attrs[0].val.clusterDim.y = 1;
    attrs[0].val.clusterDim.z = 1;
    cfg.attrs = attrs;
    cfg.numAttrs = 1;
    cudaLaunchKernelEx(&cfg, step_kernel, out);

    (void)in_sizes; (void)n_in; (void)out_size;
}

// round 13
// speedup vs baseline: 1.4874x; 1.4874x over previous
#include <cuda_runtime.h>
#include <cstdint>

// ---------------------------------------------------------------------------
// Problem constants
// ---------------------------------------------------------------------------
#define L_NUM 2
#define HS    512
#define BB    64
#define SS    1024
#define INW   512
#define ROWS  1024            // 2 gates * HS, interleaved: r = 2*h + g' (g': 0=z, 1=n)
#define SEQ_ELEMS (BB*SS*HS)

// Scan partition: 2 layers x 4 batch-groups (16 b) x 16 row-groups (64 rows)
#define NBG   4
#define GSIZE 16              // CTAs per barrier group

// ---------------------------------------------------------------------------
// Device scratch
// ---------------------------------------------------------------------------
__device__ __align__(16) float g_WG  [L_NUM*ROWS*INW];             // [l][r][i] tf32-rounded
__device__ __align__(16) float g_UG  [L_NUM*ROWS*HS];              // [l][r][o] tf32-rounded
__device__ __align__(16) float g_bias[L_NUM*ROWS];
__device__ __align__(16) float g_Gx  [(size_t)SS*L_NUM*BB*ROWS];   // 512 MB [t][l][b][r]
__device__ __align__(16) float g_Hbuf[2*L_NUM*BB*HS];              // ping-pong [p][l][b][o]
__device__ unsigned long long g_arrive[8*16];                      // 8 counters, 128B apart

__device__ __forceinline__ float rna_tf32(float x) {
    uint32_t r;
    asm("cvt.rna.tf32.f32 %0, %1;" : "=r"(r) : "f"(x));
    return __uint_as_float(r);
}

// D (4xf32) += A (m16k8 tf32, row-major) * B (k8n8 tf32, col-major)
__device__ __forceinline__ void mma_tf32(float* d, const uint32_t* a, const uint32_t* bf) {
    asm volatile(
        "mma.sync.aligned.m16n8k8.row.col.f32.tf32.tf32.f32 "
        "{%0,%1,%2,%3}, {%4,%5,%6,%7}, {%8,%9}, {%0,%1,%2,%3};"
        : "+f"(d[0]), "+f"(d[1]), "+f"(d[2]), "+f"(d[3])
        : "r"(a[0]), "r"(a[1]), "r"(a[2]), "r"(a[3]), "r"(bf[0]), "r"(bf[1]));
}

__device__ __forceinline__ void cp16(void* s, const void* g) {
    uint32_t sa = (uint32_t)__cvta_generic_to_shared(s);
    asm volatile("cp.async.cg.shared.global [%0], [%1], 16;" :: "r"(sa), "l"(g));
}

// ---------------------------------------------------------------------------
// Kernel A: combined weights (tf32-rounded) + biases
// ---------------------------------------------------------------------------
__global__ void combine_kernel(const float* __restrict__ W1, const float* __restrict__ W2,
                               const float* __restrict__ U1, const float* __restrict__ U2,
                               const float* __restrict__ dW1, const float* __restrict__ dW2,
                               const float* __restrict__ dU1, const float* __restrict__ dU2,
                               const float* __restrict__ b1, const float* __restrict__ b2)
{
    int idx = blockIdx.x * blockDim.x + threadIdx.x;   // L*ROWS*INW threads
    int l   = idx >> 19;
    int rem = idx & 524287;
    int r   = rem >> 9;
    int i   = rem & 511;
    int h   = r >> 1;
    int g   = (r & 1) + 1;                             // original gate (1=z, 2=n)

    float w1  = W1 [l*3 + g];
    float dw1 = dW1[l*3 + g];
    float u1  = U1 [l*3 + g];
    float du1 = dU1[l*3 + g];
    int src = (l*HS + h)*INW + i;
    g_WG[idx] = rna_tf32(w1*W2[src] + dw1*dW2[src]);
    g_UG[idx] = rna_tf32(u1*U2[src] + du1*dU2[src]);

    if (idx < L_NUM*ROWS) {
        int ll = idx >> 10;
        int rr = idx & 1023;
        int hh = rr >> 1;
        int gg = (rr & 1) + 1;
        g_bias[idx] = b1[ll*3*HS + gg*HS + hh] + b2[ll*3*HS + gg*HS + hh];
    }
}

// ---------------------------------------------------------------------------
// Init: h0 (L,B,HS) -> Hbuf[0][l][b][h] (same layout); reset barrier counters
// ---------------------------------------------------------------------------
__global__ void init_h_kernel(const float* __restrict__ h0)
{
    int idx = blockIdx.x * blockDim.x + threadIdx.x;   // 65536 threads
    if (idx < 8*16) g_arrive[idx] = 0ULL;
    g_Hbuf[idx] = h0[idx];
}

// ---------------------------------------------------------------------------
// Kernel B: tf32 mma GEMM with cp.async double buffering.
//   Gx[t][l][b][r] = sum_i x[b][t][i] * WG[l][r][i]
//   grid (1024, 8, 2); 8 warps: (wid&3)=m16 b-tile, (wid>>2)=64-wide r half.
// ---------------------------------------------------------------------------
#define APITCH 36
#define ABUF   (64*APITCH)
#define BBUF   (128*APITCH)
#define GEMM_SMEM ((2*ABUF + 2*BBUF)*4)   // 55296 B

__global__ void __launch_bounds__(256) gemm_x_kernel(const float* __restrict__ x)
{
    const int t  = blockIdx.x;
    const int rb = blockIdx.y * 128;
    const int l  = blockIdx.z;

    extern __shared__ __align__(16) float smem[];
    float* As = smem;                  // [2][64][36]
    float* Bs = smem + 2*ABUF;         // [2][128][36]

    const int tid  = threadIdx.x;
    const int wid  = tid >> 5;
    const int lane = tid & 31;
    const int g    = lane >> 2;
    const int tq   = lane & 3;
    const int m0   = (wid & 3) * 16;
    const int nb0  = (wid >> 2) * 64;

    const float* xa = x + (size_t)t * INW;
    const float* wb = g_WG + ((size_t)l*ROWS + rb) * INW;

    const int sa_b  = tid >> 3, sa_k = tid & 7;
    const int sb_r  = tid >> 3, sb_k = tid & 7;

    auto stage = [&](int buf, int k0) {
        float* Ad = As + buf*ABUF;
        float* Bd = Bs + buf*BBUF;
        #pragma unroll
        for (int q = 0; q < 2; ++q) {
            int b = sa_b + q*32;
            cp16(&Ad[b*APITCH + sa_k*4], xa + (size_t)b*SS*INW + k0 + sa_k*4);
        }
        #pragma unroll
        for (int q = 0; q < 4; ++q) {
            int r = sb_r + q*32;
            cp16(&Bd[r*APITCH + sb_k*4], wb + (size_t)r*INW + k0 + sb_k*4);
        }
        asm volatile("cp.async.commit_group;" ::: "memory");
    };

    float acc[8][4];
    #pragma unroll
    for (int nt = 0; nt < 8; ++nt)
        #pragma unroll
        for (int j = 0; j < 4; ++j) acc[nt][j] = 0.0f;

    stage(0, 0);

    for (int ki = 0; ki < 16; ++ki) {
        if (ki < 15) {
            stage((ki+1) & 1, (ki+1)*32);
            asm volatile("cp.async.wait_group 1;" ::: "memory");
        } else {
            asm volatile("cp.async.wait_group 0;" ::: "memory");
        }
        __syncthreads();

        const float* Ab = As + (ki & 1)*ABUF;
        const float* Bb = Bs + (ki & 1)*BBUF;
        #pragma unroll
        for (int ksi = 0; ksi < 4; ++ksi) {
            int kk = ksi*8;
            uint32_t a[4];
            a[0] = __float_as_uint(Ab[(m0+g  )*APITCH + kk + tq    ]);
            a[1] = __float_as_uint(Ab[(m0+g+8)*APITCH + kk + tq    ]);
            a[2] = __float_as_uint(Ab[(m0+g  )*APITCH + kk + tq + 4]);
            a[3] = __float_as_uint(Ab[(m0+g+8)*APITCH + kk + tq + 4]);
            #pragma unroll
            for (int nt = 0; nt < 8; ++nt) {
                int nrow = nb0 + nt*8 + g;
                uint32_t bf[2];
                bf[0] = __float_as_uint(Bb[nrow*APITCH + kk + tq    ]);
                bf[1] = __float_as_uint(Bb[nrow*APITCH + kk + tq + 4]);
                mma_tf32(acc[nt], a, bf);
            }
        }
        __syncthreads();
    }

    float* gout = g_Gx + ((size_t)(t*L_NUM + l)*BB) * ROWS + rb;
    #pragma unroll
    for (int nt = 0; nt < 8; ++nt) {
        int r = nb0 + nt*8 + 2*tq;
        __stcs((float2*)&gout[(size_t)(m0+g  )*ROWS + r], make_float2(acc[nt][0], acc[nt][1]));
        __stcs((float2*)&gout[(size_t)(m0+g+8)*ROWS + r], make_float2(acc[nt][2], acc[nt][3]));
    }
}

// ---------------------------------------------------------------------------
// Kernel C: persistent scan, software per-group barrier (R9 style, cheaper).
//   CTA (l, bg, j): 16 batches, 64 rows -> m16(b) x n64(r) x k512.
//   512 thr = 16 warps: (wid&1)=k half, (wid>>1)=n8 row tile.
//   UG B-frags in 64 regs/thread. hold carried in a register (exact fp32).
//   H stored tf32-rounded by the producer -> consumer stage is pure cp.async.
//   Barrier: __syncthreads -> tid0 red.release + acquire-spin; next-step gx
//   prefetch issued by all threads before the spin.
// ---------------------------------------------------------------------------
__global__ void __launch_bounds__(512, 1) step_kernel(float* __restrict__ out)
{
    const int tid  = threadIdx.x;
    const int lane = tid & 31;
    const int wid  = tid >> 5;
    const int g    = lane >> 2;
    const int tq   = lane & 3;

    const int bid  = blockIdx.x;
    const int l    = bid >> 6;
    const int bg   = (bid >> 4) & 3;
    const int j    = bid & 15;
    const int gid  = l*NBG + bg;
    const int rbase = j * 64;
    const int hbase = j * 32;

    const int ks    = wid & 1;          // k half
    const int nt    = wid >> 1;         // n8 tile (0..7)
    const int kbase = ks * 256;
    const int rW    = rbase + nt*8;

    __shared__ __align__(16) float Hs  [16*516];     // 33.0 KB  [bl][o]
    __shared__ __align__(16) float Dred[2*16*66];    //  8.4 KB  [ks][bl][r64]

    // --- hoist UG B-frags into registers ---
    uint32_t breg[32][2];
    {
        const float* ug = g_UG + ((size_t)l*ROWS + rW + g)*HS + kbase;
        #pragma unroll
        for (int m = 0; m < 32; ++m) {
            breg[m][0] = __float_as_uint(ug[m*8 + tq    ]);
            breg[m][1] = __float_as_uint(ug[m*8 + tq + 4]);
        }
    }

    // update-phase identity: one (h, b) pair per thread
    const int hh = tid & 31;
    const int bl = tid >> 5;
    const int bglob = bg*16 + bl;
    const float bz = g_bias[l*ROWS + rbase + 2*hh];
    const float bn = g_bias[l*ROWS + rbase + 2*hh + 1];

    // hold carried in a register (exact); only this thread produces this (h,b)
    float hold = __ldg(&g_Hbuf[(size_t)l*BB*HS + (size_t)bglob*HS + hbase + hh]);

    float* outSeq   = out;
    float* outState = out + (size_t)SEQ_ELEMS;
    unsigned long long* bar = &g_arrive[gid*16];

    const float* gxbase = g_Gx + (size_t)l*BB*ROWS + (size_t)bglob*ROWS + rbase + 2*hh;
    float2 gxv = __ldcs((const float2*)gxbase);      // t = 0

    int p = 0;
    for (int t = 0; t < SS; ++t) {
        const float* Hrd = g_Hbuf + (size_t)(p*L_NUM + l)*BB*HS;       // [b][o]
        float*       Hwr = g_Hbuf + (size_t)((1-p)*L_NUM + l)*BB*HS;

        // --- stage H slice via cp.async: 16 b x 512 o, pitch 516 ---
        #pragma unroll
        for (int q = 0; q < 4; ++q) {
            int i4   = tid + q*512;
            int row  = i4 >> 7;
            int col4 = i4 & 127;
            cp16(&Hs[row*516 + col4*4], Hrd + (size_t)(bg*16 + row)*HS + col4*4);
        }
        asm volatile("cp.async.commit_group;" ::: "memory");
        asm volatile("cp.async.wait_group 0;" ::: "memory");
        __syncthreads();

        // --- mma: m16(b) x n8(r) x k256 per warp ---
        float acc0[4] = {0,0,0,0};
        float acc1[4] = {0,0,0,0};
        #pragma unroll
        for (int m = 0; m < 32; ++m) {
            int ko = kbase + m*8;
            uint32_t a[4];
            a[0] = __float_as_uint(Hs[(g  )*516 + ko + tq    ]);
            a[1] = __float_as_uint(Hs[(g+8)*516 + ko + tq    ]);
            a[2] = __float_as_uint(Hs[(g  )*516 + ko + tq + 4]);
            a[3] = __float_as_uint(Hs[(g+8)*516 + ko + tq + 4]);
            if (m & 1) mma_tf32(acc1, a, breg[m]);
            else       mma_tf32(acc0, a, breg[m]);
        }
        {
            float* dr = &Dred[(ks*16 + g)*66 + nt*8 + 2*tq];
            *(float2*)dr          = make_float2(acc0[0]+acc1[0], acc0[1]+acc1[1]);
            *(float2*)(dr + 8*66) = make_float2(acc0[2]+acc1[2], acc0[3]+acc1[3]);
        }
        __syncthreads();

        // --- fused update: one (hh, bl) per thread ---
        {
            float2 d0 = *(const float2*)&Dred[(     bl)*66 + 2*hh];
            float2 d1 = *(const float2*)&Dred[(16 + bl)*66 + 2*hh];
            float gz = d0.x + d1.x + gxv.x + bz;
            float gn = d0.y + d1.y + gxv.y + bn;
            float z = __fdividef(1.0f, 1.0f + __expf(-gz));
            float n = 1.0f - __fdividef(2.0f, __expf(2.0f*gn) + 1.0f);
            float hnew = (1.0f - z)*n + z*hold;
            hold = hnew;
            Hwr[(size_t)bglob*HS + hbase + hh] = rna_tf32(hnew);   // producer-side rounding
            if (l == 1)
                outSeq[((size_t)bglob*SS + t)*HS + hbase + hh] = hnew;
            if (t == SS-1)
                outState[((size_t)l*BB + bglob)*HS + hbase + hh] = hnew;
        }

        __syncthreads();                               // all update stores issued

        // prefetch next-step gx (overlaps the barrier spin)
        float2 gxn = gxv;
        if (t + 1 < SS)
            gxn = __ldcs((const float2*)(gxbase + (size_t)(t+1)*L_NUM*BB*ROWS));

        if (tid == 0) {
            // release-arrive: orders this CTA's prior stores (via bar.sync HB)
            asm volatile("red.release.gpu.global.add.u64 [%0], %1;"
                         :: "l"(bar), "l"(1ULL) : "memory");
            unsigned long long target = (unsigned long long)(t+1) * GSIZE;
            unsigned long long v;
            do {
                asm volatile("ld.global.acquire.gpu.u64 %0, [%1];"
                             : "=l"(v) : "l"(bar) : "memory");
            } while (v < target);
        }
        __syncthreads();
        gxv = gxn;
        p ^= 1;
    }
}

// ---------------------------------------------------------------------------
// Launch
// ---------------------------------------------------------------------------
extern "C" void kernel_launch(void* const* d_in, const int* in_sizes, int n_in,
                              void* d_out, int out_size)
{
    const float* x   = (const float*)d_in[0];
    const float* h0  = (const float*)d_in[1];
    const float* W1  = (const float*)d_in[2];
    const float* W2  = (const float*)d_in[3];
    const float* U1  = (const float*)d_in[4];
    const float* U2  = (const float*)d_in[5];
    const float* dW1 = (const float*)d_in[6];
    const float* dW2 = (const float*)d_in[7];
    const float* dU1 = (const float*)d_in[8];
    const float* dU2 = (const float*)d_in[9];
    const float* b1  = (const float*)d_in[10];
    const float* b2  = (const float*)d_in[11];
    float* out = (float*)d_out;

    combine_kernel<<<4096, 256>>>(W1, W2, U1, U2, dW1, dW2, dU1, dU2, b1, b2);
    init_h_kernel<<<256, 256>>>(h0);

    cudaFuncSetAttribute(gemm_x_kernel, cudaFuncAttributeMaxDynamicSharedMemorySize, GEMM_SMEM);
    dim3 gg(1024, 8, 2);
    gemm_x_kernel<<<gg, 256, GEMM_SMEM>>>(x);

    step_kernel<<<128, 512>>>(out);
    (void)in_sizes; (void)n_in; (void)out_size;
}